// round 1
// baseline (speedup 1.0000x reference)
#include <cuda_runtime.h>
#include <math.h>

#define Bq 4096
#define Sq 512
#define NT 512
#define NB 128
#define RPB 32   // rows per block (4096 = 128 * 32, exact)

// smem float counts
#define SM_WHH   16384   // 64*256
#define SM_WIN   2816    // 11*256
#define SM_PRE   8192    // 32*256
#define SM_GATE  8192    // 32*256
#define SM_H     2048    // 32*64
#define SM_C     2048
#define SM_X     384     // 32*12
#define SM_WOUT  128
#define SM_TOTAL (SM_WHH+SM_WIN+SM_PRE+SM_GATE+SM_H+SM_C+SM_X+SM_WOUT+32+32)
#define SMEM_BYTES (SM_TOTAL*4)

__device__ __forceinline__ float sigf(float x){ return 1.0f/(1.0f+__expf(-x)); }
__device__ __forceinline__ float tanh_f(float x){ return 2.0f/(1.0f+__expf(-2.0f*x)) - 1.0f; }

__global__ void __launch_bounds__(NT,1)
deepar_kernel(const float* __restrict__ target,
              const float* __restrict__ covar,
              const int*   __restrict__ cats,
              const float* __restrict__ scale,
              const float* __restrict__ e0,
              const float* __restrict__ e1,
              const float* __restrict__ e2,
              const float* __restrict__ e3,
              const float* __restrict__ w_ih,
              const float* __restrict__ w_hh,
              const float* __restrict__ bias,
              const float* __restrict__ w_out,
              const float* __restrict__ b_out,
              float* __restrict__ out)
{
    extern __shared__ float sm[];
    float* whh_s   = sm;
    float* win_s   = whh_s + SM_WHH;
    float* pre_s   = win_s + SM_WIN;
    float* gates_s = pre_s + SM_PRE;
    float* h_s     = gates_s + SM_GATE;
    float* c_s     = h_s + SM_H;
    float* x_s     = c_s + SM_C;
    float* wout_s  = x_s + SM_X;
    float* sc_s    = wout_s + SM_WOUT;
    float* isc_s   = sc_s + 32;
    float* sx_s    = gates_s;   // alias: static_x [32][66], used only before t-loop

    const int tid  = threadIdx.x;
    const int row0 = blockIdx.x * RPB;

    // ---- load weights into shared ----
    for (int i = tid; i < SM_WHH; i += NT) whh_s[i] = w_hh[i];
    for (int i = tid; i < SM_WIN; i += NT) win_s[i] = w_ih[i];
    if (tid < SM_WOUT) wout_s[tid] = w_out[tid];
    if (tid < RPB){
        float s = scale[row0 + tid];
        sc_s[tid]  = s;
        isc_s[tid] = 1.0f / fmaxf(s, 1e-4f);
    }
    for (int i = tid; i < RPB*64; i += NT){ h_s[i] = 0.0f; c_s[i] = 0.0f; }

    // ---- static_x = [emb0|emb1|emb2|emb3|log1p(scale)]  -> sx_s[32][66] ----
    for (int e = tid; e < RPB*65; e += NT){
        int r = e / 65, j = e - r*65;
        int b = row0 + r;
        float v;
        if (j < 64){
            int tsel = j >> 4;
            int jj   = j & 15;
            int c    = cats[b*4 + tsel];
            const float* et = (tsel==0)?e0:(tsel==1)?e1:(tsel==2)?e2:e3;
            v = et[c*16 + jj];
        } else {
            v = log1pf(scale[b]);
        }
        sx_s[r*66 + j] = v;
    }
    __syncthreads();

    const int tx = tid & 63;   // gate group: gates 4*tx .. 4*tx+3
    const int ty = tid >> 6;   // row group: rows ty, ty+8, ty+16, ty+24

    // ---- precompute pre = bias + static_x @ w_ih[11:76]  (once) ----
    float acc[4][4];
    {
        float4 bv = *(const float4*)(bias + tx*4);
        #pragma unroll
        for (int j = 0; j < 4; j++){
            acc[j][0]=bv.x; acc[j][1]=bv.y; acc[j][2]=bv.z; acc[j][3]=bv.w;
        }
        for (int k = 0; k < 65; k++){
            float4 w = *(const float4*)(w_ih + (11+k)*256 + tx*4);
            #pragma unroll
            for (int j = 0; j < 4; j++){
                float xv = sx_s[(ty + 8*j)*66 + k];
                acc[j][0] = fmaf(xv, w.x, acc[j][0]);
                acc[j][1] = fmaf(xv, w.y, acc[j][1]);
                acc[j][2] = fmaf(xv, w.z, acc[j][2]);
                acc[j][3] = fmaf(xv, w.w, acc[j][3]);
            }
        }
        #pragma unroll
        for (int j = 0; j < 4; j++){
            float4 p; p.x=acc[j][0]; p.y=acc[j][1]; p.z=acc[j][2]; p.w=acc[j][3];
            *(float4*)(pre_s + (ty + 8*j)*256 + tx*4) = p;
        }
    }
    // NOTE: sx_s (aliased to gates_s) is dead after this point; first t-loop
    // barrier guarantees all reads completed before gates_s is overwritten.

    const float4* whh4 = (const float4*)whh_s;

    for (int t = 0; t < Sq; t++){
        // ---- phase A: per-step inputs (prev scaled target + covariates) ----
        if (tid < RPB*12){
            int r = tid / 12, j = tid - r*12;
            int b = row0 + r;
            float v = 0.0f;
            if (j == 0){
                if (t > 0) v = target[b*Sq + t - 1] * isc_s[r];
            } else if (j < 11){
                v = covar[(b*Sq + t)*10 + (j-1)];
            }
            x_s[tid] = v;
        }
        __syncthreads();

        // ---- GEMM: gates = pre + x @ w_ih[0:11] + h @ w_hh ----
        #pragma unroll
        for (int j = 0; j < 4; j++){
            float4 p = *(const float4*)(pre_s + (ty + 8*j)*256 + tx*4);
            acc[j][0]=p.x; acc[j][1]=p.y; acc[j][2]=p.z; acc[j][3]=p.w;
        }
        #pragma unroll
        for (int k = 0; k < 11; k++){
            float4 w = *(const float4*)(win_s + k*256 + tx*4);
            #pragma unroll
            for (int j = 0; j < 4; j++){
                float xv = x_s[(ty + 8*j)*12 + k];
                acc[j][0] = fmaf(xv, w.x, acc[j][0]);
                acc[j][1] = fmaf(xv, w.y, acc[j][1]);
                acc[j][2] = fmaf(xv, w.z, acc[j][2]);
                acc[j][3] = fmaf(xv, w.w, acc[j][3]);
            }
        }
        #pragma unroll 8
        for (int k = 0; k < 64; k++){
            float4 w = whh4[k*64 + tx];
            #pragma unroll
            for (int j = 0; j < 4; j++){
                float hv = h_s[(ty + 8*j)*64 + k];
                acc[j][0] = fmaf(hv, w.x, acc[j][0]);
                acc[j][1] = fmaf(hv, w.y, acc[j][1]);
                acc[j][2] = fmaf(hv, w.z, acc[j][2]);
                acc[j][3] = fmaf(hv, w.w, acc[j][3]);
            }
        }
        #pragma unroll
        for (int j = 0; j < 4; j++){
            float4 g; g.x=acc[j][0]; g.y=acc[j][1]; g.z=acc[j][2]; g.w=acc[j][3];
            *(float4*)(gates_s + (ty + 8*j)*256 + tx*4) = g;
        }
        __syncthreads();

        // ---- LSTM cell elementwise ----
        #pragma unroll
        for (int it = 0; it < (RPB*64)/NT; it++){
            int e = tid + it*NT;
            int r = e >> 6, k = e & 63;
            const float* gr = gates_s + r*256;
            float gi = sigf(gr[k]);
            float gf = sigf(gr[64 + k]);
            float gg = tanh_f(gr[128 + k]);
            float go = sigf(gr[192 + k]);
            float c  = fmaf(gf, c_s[e], gi*gg);
            c_s[e] = c;
            h_s[e] = go * tanh_f(c);
        }
        __syncthreads();

        // ---- output head: raw = h @ w_out + b_out; softplus; write ----
        if (tid < RPB*2){
            int r = tid >> 1, wsel = tid & 1;
            float a = b_out[wsel];
            const float* hr = h_s + r*64;
            #pragma unroll 8
            for (int k = 0; k < 64; k++) a = fmaf(hr[k], wout_s[k*2 + wsel], a);
            float sp = (a > 15.0f) ? a : log1pf(__expf(a));
            sp += 1e-4f;
            int b = row0 + r;
            if (wsel == 0) out[b*Sq + t] = sp * sc_s[r];
            else           out[Bq*Sq + b*Sq + t] = sp;
        }
        // next iteration's first barrier orders h_s/gates_s reuse
    }
}

extern "C" void kernel_launch(void* const* d_in, const int* in_sizes, int n_in,
                              void* d_out, int out_size)
{
    (void)in_sizes; (void)n_in; (void)out_size;
    cudaFuncSetAttribute(deepar_kernel,
                         cudaFuncAttributeMaxDynamicSharedMemorySize, SMEM_BYTES);
    deepar_kernel<<<NB, NT, SMEM_BYTES>>>(
        (const float*)d_in[0],   // target
        (const float*)d_in[1],   // covariates
        (const int*)  d_in[2],   // static_cats
        (const float*)d_in[3],   // scale
        (const float*)d_in[4],   // emb0
        (const float*)d_in[5],   // emb1
        (const float*)d_in[6],   // emb2
        (const float*)d_in[7],   // emb3
        (const float*)d_in[8],   // w_ih
        (const float*)d_in[9],   // w_hh
        (const float*)d_in[10],  // bias
        (const float*)d_in[11],  // w_out
        (const float*)d_in[12],  // b_out
        (float*)d_out);
}

// round 2
// speedup vs baseline: 1.1366x; 1.1366x over previous
#include <cuda_runtime.h>
#include <math.h>

#define Bq 4096
#define Sq 512
#define NT 512
#define NB 128
#define RPB 32   // rows per block

typedef unsigned long long ull;

// smem float counts
#define SM_WPHH  16384   // 32 kk * 256 g * 2
#define SM_WPIN  3072    // 6 kk * 256 g * 2
#define SM_PRE   8192    // 32*256
#define SM_GATE  8192    // 32*256
#define SM_H     2048
#define SM_C     2048
#define SM_X     384     // 32*12
#define SM_WOUT  128
#define SM_TOTAL (SM_WPHH+SM_WPIN+SM_PRE+SM_GATE+SM_H+SM_C+SM_X+SM_WOUT+32+32)
#define SMEM_BYTES (SM_TOTAL*4)

__device__ __forceinline__ float sigf(float x){ return 1.0f/(1.0f+__expf(-x)); }
__device__ __forceinline__ float tanh_f(float x){ return 2.0f/(1.0f+__expf(-2.0f*x)) - 1.0f; }

__device__ __forceinline__ void ffma2(ull &d, ull a, ull b){
    asm("fma.rn.f32x2 %0, %1, %2, %0;" : "+l"(d) : "l"(a), "l"(b));
}
__device__ __forceinline__ float2 unpack2(ull v){
    float2 f; asm("mov.b64 {%0,%1}, %2;" : "=f"(f.x), "=f"(f.y) : "l"(v)); return f;
}

__global__ void __launch_bounds__(NT,1)
deepar_kernel(const float* __restrict__ target,
              const float* __restrict__ covar,
              const int*   __restrict__ cats,
              const float* __restrict__ scale,
              const float* __restrict__ e0,
              const float* __restrict__ e1,
              const float* __restrict__ e2,
              const float* __restrict__ e3,
              const float* __restrict__ w_ih,
              const float* __restrict__ w_hh,
              const float* __restrict__ bias,
              const float* __restrict__ w_out,
              const float* __restrict__ b_out,
              float* __restrict__ out)
{
    extern __shared__ float sm[];
    float* wphh_s  = sm;                    // packed k-pair whh [32][256] float2
    float* wpin_s  = wphh_s + SM_WPHH;      // packed k-pair w_ih[0:12) [6][256] float2
    float* pre_s   = wpin_s + SM_WPIN;
    float* gates_s = pre_s + SM_PRE;
    float* h_s     = gates_s + SM_GATE;
    float* c_s     = h_s + SM_H;
    float* x_s     = c_s + SM_C;            // [32][12], j=11 pad=0
    float* wout_s  = x_s + SM_X;
    float* sc_s    = wout_s + SM_WOUT;
    float* isc_s   = sc_s + 32;
    float* sx_s    = gates_s;               // alias: static_x [32][66], pre-loop only

    const int tid  = threadIdx.x;
    const int row0 = blockIdx.x * RPB;

    // ---- repack weights into shared (k-pair packing for f32x2) ----
    for (int i = tid; i < 32*256; i += NT){
        int kk = i >> 8, g = i & 255;
        wphh_s[2*i]   = w_hh[(2*kk)*256 + g];
        wphh_s[2*i+1] = w_hh[(2*kk+1)*256 + g];
    }
    for (int i = tid; i < 6*256; i += NT){
        int kk = i >> 8, g = i & 255;
        wpin_s[2*i]   = w_ih[(2*kk)*256 + g];
        wpin_s[2*i+1] = (2*kk+1 < 11) ? w_ih[(2*kk+1)*256 + g] : 0.0f;
    }
    if (tid < SM_WOUT) wout_s[tid] = w_out[tid];
    if (tid < RPB){
        float s = scale[row0 + tid];
        sc_s[tid]  = s;
        isc_s[tid] = 1.0f / fmaxf(s, 1e-4f);
    }
    for (int i = tid; i < RPB*64; i += NT){ h_s[i] = 0.0f; c_s[i] = 0.0f; }

    // ---- static_x staging into sx_s[32][66] ----
    for (int e = tid; e < RPB*65; e += NT){
        int r = e / 65, j = e - r*65;
        int b = row0 + r;
        float v;
        if (j < 64){
            int tsel = j >> 4, jj = j & 15;
            int c = cats[b*4 + tsel];
            const float* et = (tsel==0)?e0:(tsel==1)?e1:(tsel==2)?e2:e3;
            v = et[c*16 + jj];
        } else {
            v = log1pf(scale[b]);
        }
        sx_s[r*66 + j] = v;
    }
    __syncthreads();

    const int tx = tid & 127;   // gate pair: gates 2tx, 2tx+1
    const int ty = tid >> 7;    // 0..3
    const int rbase = ty * 8;   // 8 consecutive rows per thread

    // ---- precompute pre = bias + static_x @ w_ih[11:76] ----
    {
        float accp[8][2];
        float b0 = bias[2*tx], b1 = bias[2*tx+1];
        #pragma unroll
        for (int j = 0; j < 8; j++){ accp[j][0]=b0; accp[j][1]=b1; }
        for (int k = 0; k < 65; k++){
            float2 w = *(const float2*)(w_ih + (11+k)*256 + 2*tx);
            #pragma unroll
            for (int j = 0; j < 8; j++){
                float xv = sx_s[(rbase+j)*66 + k];
                accp[j][0] = fmaf(xv, w.x, accp[j][0]);
                accp[j][1] = fmaf(xv, w.y, accp[j][1]);
            }
        }
        #pragma unroll
        for (int j = 0; j < 8; j++)
            ((float2*)pre_s)[(rbase+j)*128 + tx] = make_float2(accp[j][0], accp[j][1]);
    }
    // sx_s (gates_s alias) dead; next gates write is after a barrier.

    // per-thread prefetch slot for x (tid<384): r = tid/12, j = tid%12
    int xr = 0, xj = 0, xb = 0;
    float xreg = 0.0f;
    if (tid < RPB*12){
        xr = tid / 12; xj = tid - xr*12; xb = row0 + xr;
        // t=0: prev=0, covariates[t=0]
        if (xj >= 1 && xj <= 10) xreg = covar[(xb*Sq + 0)*10 + (xj-1)];
        else xreg = 0.0f;
    }

    const int hidx = tid - 448;  // head threads: tid in [448,512)

    for (int t = 0; t < Sq; t++){
        // ---- phase W: write x(t); head for step t-1 on spare threads ----
        if (tid < RPB*12){
            x_s[tid] = xreg;
        } else if (hidx >= 0 && t > 0){
            int r = hidx >> 1, wsel = hidx & 1;
            const float* hr = h_s + r*64;
            float a0=0.f,a1=0.f,a2=0.f,a3=0.f;
            #pragma unroll
            for (int k = 0; k < 64; k += 4){
                a0 = fmaf(hr[k],   wout_s[2*k     + wsel], a0);
                a1 = fmaf(hr[k+1], wout_s[2*(k+1) + wsel], a1);
                a2 = fmaf(hr[k+2], wout_s[2*(k+2) + wsel], a2);
                a3 = fmaf(hr[k+3], wout_s[2*(k+3) + wsel], a3);
            }
            float a = (a0+a1)+(a2+a3) + b_out[wsel];
            float sp = (a > 15.0f) ? a : log1pf(__expf(a));
            sp += 1e-4f;
            int b = row0 + r;
            if (wsel == 0) out[b*Sq + (t-1)] = sp * sc_s[r];
            else           out[Bq*Sq + b*Sq + (t-1)] = sp;
        }
        __syncthreads();

        // ---- phase G: prefetch x(t+1), then gates GEMM ----
        if (tid < RPB*12 && t+1 < Sq){
            if (xj == 0)                 xreg = target[xb*Sq + t] * isc_s[xr];
            else if (xj <= 10)           xreg = covar[(xb*Sq + t+1)*10 + (xj-1)];
            else                         xreg = 0.0f;
        }

        ull acc[8][2];
        #pragma unroll
        for (int j = 0; j < 8; j++){ acc[j][0] = 0ull; acc[j][1] = 0ull; }

        // x part: 6 kk (12 k incl. pad)
        {
            const ulonglong2* wpi = (const ulonglong2*)wpin_s;
            #pragma unroll
            for (int kk = 0; kk < 6; kk++){
                ulonglong2 w = wpi[kk*128 + tx];
                #pragma unroll
                for (int j = 0; j < 8; j++){
                    ull xv = *(const ull*)(x_s + (rbase+j)*12 + kk*2);
                    ffma2(acc[j][0], xv, w.x);
                    ffma2(acc[j][1], xv, w.y);
                }
            }
        }
        // h part: 32 kk, 2 kk per iter
        {
            const ulonglong2* wph = (const ulonglong2*)wphh_s;
            #pragma unroll
            for (int kk2 = 0; kk2 < 16; kk2++){
                ulonglong2 wA = wph[(2*kk2)*128 + tx];
                ulonglong2 wB = wph[(2*kk2+1)*128 + tx];
                #pragma unroll
                for (int j = 0; j < 8; j++){
                    ulonglong2 h4 = *(const ulonglong2*)(h_s + (rbase+j)*64 + kk2*4);
                    ffma2(acc[j][0], h4.x, wA.x);
                    ffma2(acc[j][1], h4.x, wA.y);
                    ffma2(acc[j][0], h4.y, wB.x);
                    ffma2(acc[j][1], h4.y, wB.y);
                }
            }
        }
        // epilogue: fold k-parity halves + pre, store gates
        #pragma unroll
        for (int j = 0; j < 8; j++){
            float2 p  = ((const float2*)pre_s)[(rbase+j)*128 + tx];
            float2 a0 = unpack2(acc[j][0]);
            float2 a1 = unpack2(acc[j][1]);
            ((float2*)gates_s)[(rbase+j)*128 + tx] =
                make_float2(a0.x + a0.y + p.x, a1.x + a1.y + p.y);
        }
        __syncthreads();

        // ---- phase E: LSTM cell elementwise ----
        #pragma unroll
        for (int it = 0; it < (RPB*64)/NT; it++){
            int e = tid + it*NT;
            int r = e >> 6, k = e & 63;
            const float* gr = gates_s + r*256;
            float gi = sigf(gr[k]);
            float gf = sigf(gr[64 + k]);
            float gg = tanh_f(gr[128 + k]);
            float go = sigf(gr[192 + k]);
            float c  = fmaf(gf, c_s[e], gi*gg);
            c_s[e] = c;
            h_s[e] = go * tanh_f(c);
        }
        __syncthreads();
    }

    // final head for t = S-1
    if (hidx >= 0){
        int r = hidx >> 1, wsel = hidx & 1;
        const float* hr = h_s + r*64;
        float a0=0.f,a1=0.f,a2=0.f,a3=0.f;
        #pragma unroll
        for (int k = 0; k < 64; k += 4){
            a0 = fmaf(hr[k],   wout_s[2*k     + wsel], a0);
            a1 = fmaf(hr[k+1], wout_s[2*(k+1) + wsel], a1);
            a2 = fmaf(hr[k+2], wout_s[2*(k+2) + wsel], a2);
            a3 = fmaf(hr[k+3], wout_s[2*(k+3) + wsel], a3);
        }
        float a = (a0+a1)+(a2+a3) + b_out[wsel];
        float sp = (a > 15.0f) ? a : log1pf(__expf(a));
        sp += 1e-4f;
        int b = row0 + r;
        if (wsel == 0) out[b*Sq + (Sq-1)] = sp * sc_s[r];
        else           out[Bq*Sq + b*Sq + (Sq-1)] = sp;
    }
}

extern "C" void kernel_launch(void* const* d_in, const int* in_sizes, int n_in,
                              void* d_out, int out_size)
{
    (void)in_sizes; (void)n_in; (void)out_size;
    cudaFuncSetAttribute(deepar_kernel,
                         cudaFuncAttributeMaxDynamicSharedMemorySize, SMEM_BYTES);
    deepar_kernel<<<NB, NT, SMEM_BYTES>>>(
        (const float*)d_in[0],   // target
        (const float*)d_in[1],   // covariates
        (const int*)  d_in[2],   // static_cats
        (const float*)d_in[3],   // scale
        (const float*)d_in[4],   // emb0
        (const float*)d_in[5],   // emb1
        (const float*)d_in[6],   // emb2
        (const float*)d_in[7],   // emb3
        (const float*)d_in[8],   // w_ih
        (const float*)d_in[9],   // w_hh
        (const float*)d_in[10],  // bias
        (const float*)d_in[11],  // w_out
        (const float*)d_in[12],  // b_out
        (float*)d_out);
}